// round 9
// baseline (speedup 1.0000x reference)
#include <cuda_runtime.h>
#include <cuda_bf16.h>
#include <cstdint>

// Problem: B=8, H=128, W=128, C=64, stride 2x2 max-unpool scatter-add.
// inputs  : [8,128,128,64] float32  -> 8,388,608 elements
// indices : [8,128,128,64] int32/int64 -> per-batch flat index into 256*256*64
// output  : [8,256,256,64] float32  -> 33,554,432 elements
static constexpr long long PER_BATCH_OUT = 256LL * 256 * 64;      // 2^22
static constexpr int NUM_BATCH = 8;
static constexpr int NSTAGE    = NUM_BATCH + 1;   // stage s: zero b=s, scatter b=s-1

static constexpr int BLOCK = 256;
// Per stage: 2048 zero blocks (2 float4/thread -> 16MB) and 2048 scatter
// blocks (2 elems/thread -> 1,048,576 elems), interleaved by blockIdx&1 so
// the scatter (long pole: atomics) gets maximal parallelism from cycle 0.
static constexpr int HBLK = 2048;
static constexpr int GRID = 2 * HBLK;   // 4096

// Runtime-detected layout flags (set by the probe block in stage 0).
__device__ int g_swap;   // 1 if d_in[0] is the indices buffer
__device__ int g_is64;   // 1 if indices are int64

// ---------------------------------------------------------------------------
// Stage kernel with PDL. Stage s zeroes batch s (independent, fire-and-forget
// STG.128) and scatters batch s-1 (loads pre-sync under the previous stage's
// atomic drain; REDs post-sync). Zero(b) one launch before scatter(b) keeps
// each 16MB atomic RMW working set L2-resident (no DRAM read-modify-write);
// __ldcs on the streams protects those L2 lines.
// ---------------------------------------------------------------------------
__global__ void __launch_bounds__(BLOCK) stage_kernel(
        const void* __restrict__ p0,
        const void* __restrict__ p1,
        float*      __restrict__ out,
        int stage) {

    cudaTriggerProgrammaticLaunchCompletion();

    const unsigned q = blockIdx.x >> 1;         // [0, 2048)

    if ((blockIdx.x & 1u) == 0u) {
        // ---- zero role (2048 blocks): batch = stage ----
        if (stage >= NUM_BATCH) return;
        float4* dst = reinterpret_cast<float4*>(out + ((long long)stage << 22));
        long long t = (long long)q * BLOCK + threadIdx.x;     // [0, 524288)
        const float4 zz = make_float4(0.f, 0.f, 0.f, 0.f);
        dst[t]            = zz;
        dst[t + 524288LL] = zz;
        return;
    }

    // ---- scatter role (2048 blocks): batch = stage - 1, 2 elems/thread ----
    if (stage == 0) {
        // Probe (one block): detect which buffer is indices + their width.
        // Indices are small non-negative ints (< 2^22); normal float bits
        // read as int32 are ~1e9 or negative. int64 < 2^22 has odd words 0.
        if (q != 0) return;
        const int* a = (const int*)p0;
        const int* b = (const int*)p1;
        int k = threadIdx.x;
        bool ok_a = (a[k] >= 0 && a[k] < (int)PER_BATCH_OUT);
        bool ok_b = (b[k] >= 0 && b[k] < (int)PER_BATCH_OUT);
        int ca = __syncthreads_count(ok_a);
        int cb = __syncthreads_count(ok_b);
        int swap = (ca > cb) ? 1 : 0;
        const int* idx = swap ? a : b;
        int nz = __syncthreads_count(idx[2 * k + 1] != 0);
        if (k == 0) { g_swap = swap; g_is64 = (nz == 0) ? 1 : 0; }
        return;
    }

    const long long b  = stage - 1;
    const long long u  = (long long)q * BLOCK + threadIdx.x;   // [0, 524288)
    const long long pr = (b << 19) + u;                        // global 2-elem pair id
    const long long i  = pr << 1;                              // element index

    // Speculative flag read (stable after stage 0; deterministic on replays).
    int swap_s = __ldcg(&g_swap);
    int is64_s = __ldcg(&g_is64);

    const float* in  = (const float*)(swap_s ? p1 : p0);
    const void*  idx = swap_s ? p0 : p1;

    // Independent front-batched loads, pre-sync: latency hides under the
    // previous stage's atomic drain.
    float2 v = __ldcs(reinterpret_cast<const float2*>(in + i));
    long long j0, j1;
    if (is64_s) {
        const longlong2 a = __ldcs(reinterpret_cast<const longlong2*>(idx) + pr);
        j0 = a.x; j1 = a.y;
    } else {
        const int2 a = __ldcs(reinterpret_cast<const int2*>(idx) + pr);
        j0 = a.x; j1 = a.y;
    }

    // Wait for the previous grid (which zeroed batch b) to complete.
    cudaGridDependencySynchronize();

    // Re-check flags; reload if the speculation was wrong (at most once ever,
    // while stage 0's probe was still in flight).
    int swap_c = __ldcg(&g_swap);
    int is64_c = __ldcg(&g_is64);
    if (swap_c != swap_s || is64_c != is64_s) {
        const float* in2  = (const float*)(swap_c ? p1 : p0);
        const void*  idx2 = swap_c ? p0 : p1;
        v = __ldcs(reinterpret_cast<const float2*>(in2 + i));
        if (is64_c) {
            const longlong2 a = __ldcs(reinterpret_cast<const longlong2*>(idx2) + pr);
            j0 = a.x; j1 = a.y;
        } else {
            const int2 a = __ldcs(reinterpret_cast<const int2*>(idx2) + pr);
            j0 = a.x; j1 = a.y;
        }
    }

    float* ob = out + (b << 22);   // batch base (both elems same batch)
    if ((unsigned long long)j0 < (unsigned long long)PER_BATCH_OUT) atomicAdd(ob + j0, v.x);
    if ((unsigned long long)j1 < (unsigned long long)PER_BATCH_OUT) atomicAdd(ob + j1, v.y);
}

extern "C" void kernel_launch(void* const* d_in, const int* in_sizes, int n_in,
                              void* d_out, int out_size) {
    const void* p0 = d_in[0];
    const void* p1 = d_in[1];
    float* out = (float*)d_out;

    cudaLaunchAttribute attr[1];
    attr[0].id = cudaLaunchAttributeProgrammaticStreamSerialization;
    attr[0].val.programmaticStreamSerializationAllowed = 1;

    cudaLaunchConfig_t cfg = {};
    cfg.gridDim  = dim3(GRID, 1, 1);
    cfg.blockDim = dim3(BLOCK, 1, 1);
    cfg.dynamicSmemBytes = 0;
    cfg.stream = 0;
    cfg.attrs = attr;
    cfg.numAttrs = 1;

    // Stage 0: zero batch 0 + probe. Stages 1..7: zero b + scatter b-1.
    // Stage 8: scatter batch 7 only. PDL overlaps adjacent stages.
    for (int stage = 0; stage < NSTAGE; stage++) {
        cudaLaunchKernelEx(&cfg, stage_kernel, p0, p1, out, stage);
    }
}

// round 10
// speedup vs baseline: 1.0926x; 1.0926x over previous
#include <cuda_runtime.h>
#include <cuda_bf16.h>
#include <cstdint>

// Problem: B=8, H=128, W=128, C=64, stride 2x2 max-unpool scatter-add.
// inputs  : [8,128,128,64] float32  -> 8,388,608 elements
// indices : [8,128,128,64] int32/int64 -> per-batch flat index into 256*256*64
// output  : [8,256,256,64] float32  -> 33,554,432 elements
static constexpr long long PER_BATCH_OUT = 256LL * 256 * 64;      // 2^22
static constexpr long long TOTAL_IN      = 8LL << 20;             // 8,388,608
static constexpr long long TOTAL_OUT     = 8LL << 22;             // 33,554,432

static constexpr int BLOCK = 256;
static constexpr int ZGRID = 8192;   // 8192*256 threads * 4 float4 = 8,388,608 float4
static constexpr int SGRID = 4096;   // 4096*256 threads * 8 elems  = 8,388,608 elems

// Runtime-detected layout flags (set by the probe in the zero kernel).
__device__ int g_swap;   // 1 if d_in[0] is the indices buffer
__device__ int g_is64;   // 1 if indices are int64

// ---------------------------------------------------------------------------
// Kernel 1: zero the whole output (dirties all 134MB of output lines in L2)
// + probe the index layout in block 0. Triggers PDL completion immediately so
// the scatter kernel co-schedules and issues its streaming loads under us.
// ---------------------------------------------------------------------------
__global__ void __launch_bounds__(BLOCK) zero_probe_kernel(
        const void* __restrict__ p0,
        const void* __restrict__ p1,
        float*      __restrict__ out) {

    cudaTriggerProgrammaticLaunchCompletion();

    const long long t = (long long)blockIdx.x * BLOCK + threadIdx.x;  // [0, 2^21)
    float4* dst = reinterpret_cast<float4*>(out);
    const float4 zz = make_float4(0.f, 0.f, 0.f, 0.f);
    const long long stride = (long long)ZGRID * BLOCK;                // 2,097,152
    #pragma unroll
    for (int r = 0; r < 4; r++)
        dst[t + (long long)r * stride] = zz;

    // Probe (block 0): which buffer holds indices, and are they int64?
    // Indices are small non-negative ints (< 2^22); normal float bits read as
    // int32 are ~1e9 or negative. int64 < 2^22 has all odd 32-bit words == 0.
    if (blockIdx.x == 0) {
        const int* a = (const int*)p0;
        const int* b = (const int*)p1;
        int k = threadIdx.x;
        bool ok_a = (a[k] >= 0 && a[k] < (int)PER_BATCH_OUT);
        bool ok_b = (b[k] >= 0 && b[k] < (int)PER_BATCH_OUT);
        int ca = __syncthreads_count(ok_a);
        int cb = __syncthreads_count(ok_b);
        int swap = (ca > cb) ? 1 : 0;
        const int* idx = swap ? a : b;
        int nz = __syncthreads_count(idx[2 * k + 1] != 0);
        if (k == 0) { g_swap = swap; g_is64 = (nz == 0) ? 1 : 0; }
    }
}

// ---------------------------------------------------------------------------
// Kernel 2: full scatter, 8 elements/thread. All streaming loads (2x float4 +
// 2x int4 or 4x longlong2, evict-first) issue PRE-sync so their latency hides
// under the zero kernel; after cudaGridDependencySynchronize (zeroes + probe
// complete, output lines dirty in L2) the 8 REDs fire into L2-resident lines.
// ---------------------------------------------------------------------------
__global__ void __launch_bounds__(BLOCK) scatter_kernel(
        const void* __restrict__ p0,
        const void* __restrict__ p1,
        float*      __restrict__ out) {

    cudaTriggerProgrammaticLaunchCompletion();

    const long long t = (long long)blockIdx.x * BLOCK + threadIdx.x;  // [0, 2^20)
    const long long i = t << 3;                                       // 8 elems

    // Speculative flag read (deterministic; stable on all graph replays).
    int swap_s = __ldcg(&g_swap);
    int is64_s = __ldcg(&g_is64);

    const float* in  = (const float*)(swap_s ? p1 : p0);
    const void*  idx = swap_s ? p0 : p1;

    // Front-batched independent loads (max MLP), pre-sync.
    float4 v0 = __ldcs(reinterpret_cast<const float4*>(in + i));
    float4 v1 = __ldcs(reinterpret_cast<const float4*>(in + i + 4));
    long long j[8];
    if (is64_s) {
        #pragma unroll
        for (int r = 0; r < 4; r++) {
            const longlong2 a = __ldcs(reinterpret_cast<const longlong2*>(idx) + (i >> 1) + r);
            j[2 * r] = a.x; j[2 * r + 1] = a.y;
        }
    } else {
        const int4 a0 = __ldcs(reinterpret_cast<const int4*>(idx) + (i >> 2));
        const int4 a1 = __ldcs(reinterpret_cast<const int4*>(idx) + (i >> 2) + 1);
        j[0] = a0.x; j[1] = a0.y; j[2] = a0.z; j[3] = a0.w;
        j[4] = a1.x; j[5] = a1.y; j[6] = a1.z; j[7] = a1.w;
    }

    // Wait for the zero kernel (and probe) to fully complete.
    cudaGridDependencySynchronize();

    // Re-check flags; reload if speculation was wrong (at most once ever,
    // while the probe was still in flight; identical on every replay after).
    int swap_c = __ldcg(&g_swap);
    int is64_c = __ldcg(&g_is64);
    if (swap_c != swap_s || is64_c != is64_s) {
        const float* in2  = (const float*)(swap_c ? p1 : p0);
        const void*  idx2 = swap_c ? p0 : p1;
        v0 = __ldcs(reinterpret_cast<const float4*>(in2 + i));
        v1 = __ldcs(reinterpret_cast<const float4*>(in2 + i + 4));
        if (is64_c) {
            #pragma unroll
            for (int r = 0; r < 4; r++) {
                const longlong2 a = __ldcs(reinterpret_cast<const longlong2*>(idx2) + (i >> 1) + r);
                j[2 * r] = a.x; j[2 * r + 1] = a.y;
            }
        } else {
            const int4 a0 = __ldcs(reinterpret_cast<const int4*>(idx2) + (i >> 2));
            const int4 a1 = __ldcs(reinterpret_cast<const int4*>(idx2) + (i >> 2) + 1);
            j[0] = a0.x; j[1] = a0.y; j[2] = a0.z; j[3] = a0.w;
            j[4] = a1.x; j[5] = a1.y; j[6] = a1.z; j[7] = a1.w;
        }
    }

    // All 8 elements share one batch (8 | 2^20).
    float* ob = out + ((i >> 20) << 22);
    const float vv[8] = {v0.x, v0.y, v0.z, v0.w, v1.x, v1.y, v1.z, v1.w};
    #pragma unroll
    for (int r = 0; r < 8; r++)
        if ((unsigned long long)j[r] < (unsigned long long)PER_BATCH_OUT)
            atomicAdd(ob + j[r], vv[r]);
}

extern "C" void kernel_launch(void* const* d_in, const int* in_sizes, int n_in,
                              void* d_out, int out_size) {
    const void* p0 = d_in[0];
    const void* p1 = d_in[1];
    float* out = (float*)d_out;

    cudaLaunchAttribute attr[1];
    attr[0].id = cudaLaunchAttributeProgrammaticStreamSerialization;
    attr[0].val.programmaticStreamSerializationAllowed = 1;

    cudaLaunchConfig_t zcfg = {};
    zcfg.gridDim  = dim3(ZGRID, 1, 1);
    zcfg.blockDim = dim3(BLOCK, 1, 1);
    zcfg.stream = 0;
    zcfg.attrs = attr;
    zcfg.numAttrs = 1;

    cudaLaunchConfig_t scfg = {};
    scfg.gridDim  = dim3(SGRID, 1, 1);
    scfg.blockDim = dim3(BLOCK, 1, 1);
    scfg.stream = 0;
    scfg.attrs = attr;
    scfg.numAttrs = 1;

    cudaLaunchKernelEx(&zcfg, zero_probe_kernel, p0, p1, out);
    cudaLaunchKernelEx(&scfg, scatter_kernel,    p0, p1, out);
}